// round 1
// baseline (speedup 1.0000x reference)
#include <cuda_runtime.h>

// SNN elementwise state update, B*D = 4096*4096 fp32.
// Inputs (metadata order): total_input_current, v, x, j, ref_count
// Outputs packed in d_out: [v | s | x | j | ref_count], each B*D floats.
//
// Constants (CFG): dt=0.5, kappa_j=0.2, tau_j=8, gamma_m=0.1, R_m=5,
//                  tau_m=10, thresh=1, t_ref=2, tau_tr=20

__device__ __forceinline__ void snn_update(float I, float& v, float& x,
                                           float& j, float& rc, float& s) {
    const float dt       = 0.5f;
    const float dt_tauj  = 0.0625f;   // 0.5/8
    const float kappa_j  = 0.2f;
    const float dt_taum  = 0.05f;     // 0.5/10
    const float gamma_m  = 0.1f;
    const float R_m      = 5.0f;
    const float thresh   = 1.0f;
    const float t_ref    = 2.0f;
    const float tau_tr   = 20.0f;

    // refractory countdown
    rc = fmaxf(rc - dt, 0.0f);
    // synaptic current leaky integration
    j = j + dt_tauj * (-kappa_j * j + I);
    // membrane update, frozen while refractory
    float is_ref = (rc > 0.0f) ? 1.0f : 0.0f;
    v = v + (1.0f - is_ref) * dt_taum * (-gamma_m * v + R_m * j);
    // threshold -> spike, reset
    float spikes = (v > thresh) ? 1.0f : 0.0f;
    s = spikes;
    v = v * (1.0f - spikes);
    // refractory entry
    rc = (spikes > 0.0f) ? t_ref : rc;
    // spike trace
    x = x - x / tau_tr + spikes;
}

__global__ void __launch_bounds__(256)
snn_kernel(const float4* __restrict__ in_I,
           const float4* __restrict__ in_v,
           const float4* __restrict__ in_x,
           const float4* __restrict__ in_j,
           const float4* __restrict__ in_rc,
           float4* __restrict__ out_v,
           float4* __restrict__ out_s,
           float4* __restrict__ out_x,
           float4* __restrict__ out_j,
           float4* __restrict__ out_rc,
           int n4) {
    int idx = blockIdx.x * blockDim.x + threadIdx.x;
    if (idx >= n4) return;

    float4 I  = in_I[idx];
    float4 v  = in_v[idx];
    float4 x  = in_x[idx];
    float4 j  = in_j[idx];
    float4 rc = in_rc[idx];
    float4 s;

    snn_update(I.x, v.x, x.x, j.x, rc.x, s.x);
    snn_update(I.y, v.y, x.y, j.y, rc.y, s.y);
    snn_update(I.z, v.z, x.z, j.z, rc.z, s.z);
    snn_update(I.w, v.w, x.w, j.w, rc.w, s.w);

    out_v[idx]  = v;
    out_s[idx]  = s;
    out_x[idx]  = x;
    out_j[idx]  = j;
    out_rc[idx] = rc;
}

extern "C" void kernel_launch(void* const* d_in, const int* in_sizes, int n_in,
                              void* d_out, int out_size) {
    const float4* I  = (const float4*)d_in[0];
    const float4* v  = (const float4*)d_in[1];
    const float4* x  = (const float4*)d_in[2];
    const float4* j  = (const float4*)d_in[3];
    const float4* rc = (const float4*)d_in[4];

    int n  = in_sizes[0];        // B*D elements
    int n4 = n / 4;              // float4 quads (B*D = 16,777,216 is divisible by 4)

    float* out = (float*)d_out;  // [v | s | x | j | ref_count]
    float4* ov  = (float4*)(out + 0L * n);
    float4* os  = (float4*)(out + 1L * n);
    float4* ox  = (float4*)(out + 2L * n);
    float4* oj  = (float4*)(out + 3L * n);
    float4* orc = (float4*)(out + 4L * n);

    int threads = 256;
    int blocks  = (n4 + threads - 1) / threads;
    snn_kernel<<<blocks, threads>>>(I, v, x, j, rc, ov, os, ox, oj, orc, n4);
}